// round 6
// baseline (speedup 1.0000x reference)
#include <cuda_runtime.h>
#include <math.h>

#define N_NODES 100000
#define N_EDGES 1600000

// ---------------- scratch (device globals; no allocation allowed) ----------
__device__ float g_agg1[(size_t)N_NODES * 64];   // mean-agg of x   (sum, scaled later)
__device__ float g_h   [(size_t)N_NODES * 128];  // layer-1 output
__device__ float g_t   [(size_t)N_NODES * 64];   // h @ W_l2 (projected, pre-aggregation)
__device__ float g_agg2[(size_t)N_NODES * 64];   // agg of t
__device__ int   g_cnt [N_NODES];                // in-degree per node

// ---------------- f32x2 helpers --------------------------------------------
__device__ __forceinline__ unsigned long long pk2(float x, float y) {
    unsigned long long r;
    asm("mov.b64 %0, {%1, %2};" : "=l"(r) : "f"(x), "f"(y));
    return r;
}
__device__ __forceinline__ void fma2(unsigned long long& d, unsigned long long a,
                                     unsigned long long b) {
    asm("fma.rn.f32x2 %0, %1, %2, %3;" : "=l"(d) : "l"(a), "l"(b), "l"(d));
}
__device__ __forceinline__ float2 upk2(unsigned long long v) {
    float2 f;
    asm("mov.b64 {%0, %1}, %2;" : "=f"(f.x), "=f"(f.y) : "l"(v));
    return f;
}

// ---------------- degree count ----------------------------------------------
__global__ void count_kernel(const int* __restrict__ dst) {
    int i = blockIdx.x * blockDim.x + threadIdx.x;
    if (i < N_EDGES) atomicAdd(&g_cnt[dst[i]], 1);
}

// ---------------- edge scatter: agg[dst] += feat[src], 64 floats/edge -------
// 16 threads per edge, one float4 + one red.global.add.v4 each.
__global__ void scatter_kernel(const float* __restrict__ feat,
                               const int* __restrict__ src,
                               const int* __restrict__ dst,
                               float* __restrict__ agg) {
    int gid = blockIdx.x * blockDim.x + threadIdx.x;
    int e = gid >> 4;
    int lane = gid & 15;
    if (e >= N_EDGES) return;
    int s = __ldg(&src[e]);
    int d = __ldg(&dst[e]);
    float4 v = __ldg((const float4*)(feat + (size_t)s * 64) + lane);
    float* p = agg + (size_t)d * 64 + lane * 4;
    asm volatile("red.global.add.v4.f32 [%0], {%1, %2, %3, %4};"
                 :: "l"(p), "f"(v.x), "f"(v.y), "f"(v.z), "f"(v.w)
                 : "memory");
}

// ---------------- fused 128x128 GEMM per 64-row tile -------------------------
// MODE 1: h = relu([agg1/cnt | x] @ [W_l1 ; W_r1] + b1)          (K=64+64, C=128)
// MODE 2: [t | r2] = h @ [W_l2 | W_r2];  t -> outA, r2+b2 -> outB (K=128, C=64+64)
template <int MODE>
__global__ void gemm_kernel(const float* __restrict__ A0,   // agg1 (M1) / h (M2)
                            const float* __restrict__ A1,   // x (M1) / unused
                            const float* __restrict__ Wa,
                            const float* __restrict__ Wb,
                            const float* __restrict__ bias,
                            float* __restrict__ outA,
                            float* __restrict__ outB) {
    extern __shared__ float smem[];
    float* sW = smem;              // 128 x 128
    float* sA = smem + 128 * 128;  // 64 x 128
    float* sB = sA + 64 * 128;     // 128
    const int tid = threadIdx.x;
    const int base = blockIdx.x * 64;

    // ---- stage W (16384 floats) ----
    {
        float4* sw4 = (float4*)sW;
        if (MODE == 1) {
            const float4* wa4 = (const float4*)Wa;   // [64][128]
            const float4* wb4 = (const float4*)Wb;
#pragma unroll
            for (int i = 0; i < 8; i++) sw4[tid + 256 * i] = __ldg(&wa4[tid + 256 * i]);
#pragma unroll
            for (int i = 0; i < 8; i++) sw4[2048 + tid + 256 * i] = __ldg(&wb4[tid + 256 * i]);
            if (tid < 128) sB[tid] = bias[tid];
        } else {
            const float4* wa4 = (const float4*)Wa;   // [128][64] -> 16 f4 per row
            const float4* wb4 = (const float4*)Wb;
#pragma unroll
            for (int i = 0; i < 16; i++) {
                int p = tid + 256 * i;       // f4 index in sW; k = p>>5, cq = p&31
                int k = p >> 5, cq = p & 31;
                sw4[p] = (cq < 16) ? __ldg(&wa4[k * 16 + cq])
                                   : __ldg(&wb4[k * 16 + (cq - 16)]);
            }
            if (tid < 128) sB[tid] = (tid < 64) ? 0.0f : bias[tid - 64];
        }
    }

    // ---- stage A tile (64 rows x 128 k) ----
    {
        const int kc = tid & 31;   // float4 chunk along K
        const int r = tid >> 5;
#pragma unroll
        for (int j = 0; j < 8; j++) {
            int rl = r + 8 * j;
            int row = base + rl;
            float4 v = make_float4(0.f, 0.f, 0.f, 0.f);
            if (row < N_NODES) {
                if (MODE == 1) {
                    if (kc < 16) {
                        v = __ldg((const float4*)(A0 + (size_t)row * 64) + kc);
                        float s = 1.0f / (float)max(g_cnt[row], 1);
                        v.x *= s; v.y *= s; v.z *= s; v.w *= s;
                    } else {
                        v = __ldg((const float4*)(A1 + (size_t)row * 64) + (kc - 16));
                    }
                } else {
                    v = __ldg((const float4*)(A0 + (size_t)row * 128) + kc);
                }
            }
            *((float4*)(sA + rl * 128) + kc) = v;
        }
    }
    __syncthreads();

    // ---- compute: each thread = 8 rows x 4 cols, f32x2 packed accumulators ----
    const int cx = tid & 31;    // cols 4cx..4cx+3
    const int ry = tid >> 5;    // rows ry, ry+8, ..., ry+56
    unsigned long long acc[8][2];
#pragma unroll
    for (int j = 0; j < 8; j++) { acc[j][0] = 0ull; acc[j][1] = 0ull; }

    for (int kb = 0; kb < 128; kb += 4) {
        float4 a[8];
#pragma unroll
        for (int j = 0; j < 8; j++)
            a[j] = *((const float4*)(sA + (ry + 8 * j) * 128) + (kb >> 2));
#pragma unroll
        for (int kk = 0; kk < 4; kk++) {
            float4 w = *((const float4*)(sW + (kb + kk) * 128) + cx);
            unsigned long long w01 = pk2(w.x, w.y);
            unsigned long long w23 = pk2(w.z, w.w);
#pragma unroll
            for (int j = 0; j < 8; j++) {
                float av = (kk == 0) ? a[j].x : (kk == 1) ? a[j].y
                         : (kk == 2) ? a[j].z : a[j].w;
                unsigned long long a2 = pk2(av, av);
                fma2(acc[j][0], a2, w01);
                fma2(acc[j][1], a2, w23);
            }
        }
    }

    // ---- epilogue ----
    const int c = 4 * cx;
    const float b0 = sB[c], b1v = sB[c + 1], b2v = sB[c + 2], b3v = sB[c + 3];
#pragma unroll
    for (int j = 0; j < 8; j++) {
        int row = base + ry + 8 * j;
        if (row >= N_NODES) continue;
        float2 v01 = upk2(acc[j][0]);
        float2 v23 = upk2(acc[j][1]);
        float o0 = v01.x + b0, o1 = v01.y + b1v, o2 = v23.x + b2v, o3 = v23.y + b3v;
        if (MODE == 1) {
            o0 = fmaxf(o0, 0.f); o1 = fmaxf(o1, 0.f);
            o2 = fmaxf(o2, 0.f); o3 = fmaxf(o3, 0.f);
            *((float4*)(outA + (size_t)row * 128) + cx) = make_float4(o0, o1, o2, o3);
        } else {
            if (c < 64)
                *((float4*)(outA + (size_t)row * 64) + cx) = make_float4(o0, o1, o2, o3);
            else
                *((float4*)(outB + (size_t)row * 64) + (cx - 16)) = make_float4(o0, o1, o2, o3);
        }
    }
}

// ---------------- finalize: out = sigmoid(agg2/cnt + r2) --------------------
__global__ void finalize_kernel(const float* __restrict__ agg2,
                                float* __restrict__ out) {
    int i = blockIdx.x * blockDim.x + threadIdx.x;   // float4 index
    if (i >= N_NODES * 16) return;
    int row = i >> 4;
    float s = 1.0f / (float)max(g_cnt[row], 1);
    float4 a = __ldg((const float4*)agg2 + i);
    float4 r = ((const float4*)out)[i];
    float4 o;
    o.x = 1.0f / (1.0f + expf(-(a.x * s + r.x)));
    o.y = 1.0f / (1.0f + expf(-(a.y * s + r.y)));
    o.z = 1.0f / (1.0f + expf(-(a.z * s + r.z)));
    o.w = 1.0f / (1.0f + expf(-(a.w * s + r.w)));
    ((float4*)out)[i] = o;
}

// ---------------- launch ------------------------------------------------------
extern "C" void kernel_launch(void* const* d_in, const int* in_sizes, int n_in,
                              void* d_out, int out_size) {
    const float* x    = (const float*)d_in[0];
    const int*   ei   = (const int*)d_in[1];
    const float* W_l1 = (const float*)d_in[2];
    const float* W_r1 = (const float*)d_in[3];
    const float* b1   = (const float*)d_in[4];
    const float* W_l2 = (const float*)d_in[5];
    const float* W_r2 = (const float*)d_in[6];
    const float* b2   = (const float*)d_in[7];
    const int* src = ei;
    const int* dst = ei + N_EDGES;
    float* out = (float*)d_out;

    void *p_agg1, *p_agg2, *p_cnt, *p_h, *p_t;
    cudaGetSymbolAddress(&p_agg1, g_agg1);
    cudaGetSymbolAddress(&p_agg2, g_agg2);
    cudaGetSymbolAddress(&p_cnt,  g_cnt);
    cudaGetSymbolAddress(&p_h,    g_h);
    cudaGetSymbolAddress(&p_t,    g_t);

    cudaMemsetAsync(p_cnt,  0, (size_t)N_NODES * sizeof(int));
    cudaMemsetAsync(p_agg1, 0, (size_t)N_NODES * 64 * sizeof(float));
    cudaMemsetAsync(p_agg2, 0, (size_t)N_NODES * 64 * sizeof(float));

    count_kernel<<<(N_EDGES + 255) / 256, 256>>>(dst);
    scatter_kernel<<<(N_EDGES * 16) / 256, 256>>>(x, src, dst, (float*)p_agg1);

    const int smem = (128 * 128 + 64 * 128 + 128) * (int)sizeof(float);
    cudaFuncSetAttribute(gemm_kernel<1>, cudaFuncAttributeMaxDynamicSharedMemorySize, smem);
    cudaFuncSetAttribute(gemm_kernel<2>, cudaFuncAttributeMaxDynamicSharedMemorySize, smem);
    const int gemm_blocks = (N_NODES + 63) / 64;

    gemm_kernel<1><<<gemm_blocks, 256, smem>>>((const float*)p_agg1, x,
                                               W_l1, W_r1, b1,
                                               (float*)p_h, (float*)nullptr);
    gemm_kernel<2><<<gemm_blocks, 256, smem>>>((const float*)p_h, (const float*)nullptr,
                                               W_l2, W_r2, b2,
                                               (float*)p_t, out);

    scatter_kernel<<<(N_EDGES * 16) / 256, 256>>>((const float*)p_t, src, dst,
                                                  (float*)p_agg2);
    finalize_kernel<<<(N_NODES * 16 + 255) / 256, 256>>>((const float*)p_agg2, out);
}

// round 7
// speedup vs baseline: 1.2231x; 1.2231x over previous
#include <cuda_runtime.h>
#include <math.h>

#define N_NODES 100000
#define N_EDGES 1600000
#define SCAN_B 512
#define NB ((N_NODES + SCAN_B - 1) / SCAN_B)   // 196

// ---------------- scratch (device globals; no allocation allowed) ----------
__device__ float g_agg1[(size_t)N_NODES * 64];   // mean-agg of x
__device__ float g_h   [(size_t)N_NODES * 128];  // layer-1 output
__device__ float g_t   [(size_t)N_NODES * 64];   // h @ W_l2 (projected)
__device__ float g_agg2[(size_t)N_NODES * 64];   // mean-agg of t
__device__ int   g_cnt [N_NODES];
__device__ int   g_off [N_NODES];
__device__ int   g_pos [N_NODES];
__device__ int   g_adj [N_EDGES];
__device__ int   g_blocksum[NB];
__device__ int   g_blockoff[NB];

// ---------------- f32x2 helpers --------------------------------------------
__device__ __forceinline__ unsigned long long pk2(float x, float y) {
    unsigned long long r;
    asm("mov.b64 %0, {%1, %2};" : "=l"(r) : "f"(x), "f"(y));
    return r;
}
__device__ __forceinline__ void fma2(unsigned long long& d, unsigned long long a,
                                     unsigned long long b) {
    asm("fma.rn.f32x2 %0, %1, %2, %3;" : "=l"(d) : "l"(a), "l"(b), "l"(d));
}
__device__ __forceinline__ float2 upk2(unsigned long long v) {
    float2 f;
    asm("mov.b64 {%0, %1}, %2;" : "=f"(f.x), "=f"(f.y) : "l"(v));
    return f;
}

// ---------------- CSR construction ------------------------------------------
__global__ void count_kernel(const int* __restrict__ dst) {
    int i = blockIdx.x * blockDim.x + threadIdx.x;
    if (i < N_EDGES) atomicAdd(&g_cnt[dst[i]], 1);
}

__global__ void reduce_kernel() {   // grid NB, block SCAN_B
    __shared__ int s[SCAN_B / 32];
    int i = blockIdx.x * SCAN_B + threadIdx.x;
    int v = (i < N_NODES) ? g_cnt[i] : 0;
#pragma unroll
    for (int o = 16; o > 0; o >>= 1) v += __shfl_down_sync(0xffffffffu, v, o);
    if ((threadIdx.x & 31) == 0) s[threadIdx.x >> 5] = v;
    __syncthreads();
    if (threadIdx.x == 0) {
        int t = 0;
#pragma unroll
        for (int w = 0; w < SCAN_B / 32; w++) t += s[w];
        g_blocksum[blockIdx.x] = t;
    }
}

__global__ void scanblock_kernel() {   // 1 block, 256 threads
    __shared__ int s[256];
    int v = (threadIdx.x < NB) ? g_blocksum[threadIdx.x] : 0;
    s[threadIdx.x] = v;
    __syncthreads();
    for (int d = 1; d < 256; d <<= 1) {
        int t = (threadIdx.x >= d) ? s[threadIdx.x - d] : 0;
        __syncthreads();
        s[threadIdx.x] += t;
        __syncthreads();
    }
    if (threadIdx.x < NB)
        g_blockoff[threadIdx.x] = (threadIdx.x == 0) ? 0 : s[threadIdx.x - 1];
}

__global__ void scatteroff_kernel() {   // grid NB, block SCAN_B
    __shared__ int s[SCAN_B];
    int b = blockIdx.x;
    int i = b * SCAN_B + threadIdx.x;
    int v = (i < N_NODES) ? g_cnt[i] : 0;
    s[threadIdx.x] = v;
    __syncthreads();
    for (int d = 1; d < SCAN_B; d <<= 1) {
        int t = (threadIdx.x >= d) ? s[threadIdx.x - d] : 0;
        __syncthreads();
        s[threadIdx.x] += t;
        __syncthreads();
    }
    if (i < N_NODES) {
        int excl = s[threadIdx.x] - v + g_blockoff[b];
        g_off[i] = excl;
        g_pos[i] = excl;
    }
}

__global__ void fill_kernel(const int* __restrict__ src, const int* __restrict__ dst) {
    int e = blockIdx.x * blockDim.x + threadIdx.x;
    if (e < N_EDGES) {
        int d = dst[e];
        int p = atomicAdd(&g_pos[d], 1);
        g_adj[p] = src[e];
    }
}

// ---------------- pull aggregation: out[n] = mean_{s in adj(n)} feat[s] ------
// one warp per node; lanes split into 2 halves of 16, each half walks every
// other neighbor with 2-deep load pipelining; 16 float4 chunks cover 64 ch.
__global__ void agg_kernel(const float* __restrict__ feat, float* __restrict__ outp) {
    int node = blockIdx.x * 8 + (threadIdx.x >> 5);
    if (node >= N_NODES) return;
    int lane = threadIdx.x & 31;
    int half = lane >> 4;
    int q = lane & 15;
    int off = __ldg(&g_off[node]);
    int c = __ldg(&g_cnt[node]);
    float4 acc = make_float4(0.f, 0.f, 0.f, 0.f);
    int i = half;
    for (; i + 2 < c; i += 4) {
        int s0 = __ldg(&g_adj[off + i]);
        int s1 = __ldg(&g_adj[off + i + 2]);
        float4 v0 = __ldg((const float4*)(feat + (size_t)s0 * 64) + q);
        float4 v1 = __ldg((const float4*)(feat + (size_t)s1 * 64) + q);
        acc.x += v0.x + v1.x; acc.y += v0.y + v1.y;
        acc.z += v0.z + v1.z; acc.w += v0.w + v1.w;
    }
    if (i < c) {
        int s0 = __ldg(&g_adj[off + i]);
        float4 v0 = __ldg((const float4*)(feat + (size_t)s0 * 64) + q);
        acc.x += v0.x; acc.y += v0.y; acc.z += v0.z; acc.w += v0.w;
    }
    acc.x += __shfl_xor_sync(0xffffffffu, acc.x, 16);
    acc.y += __shfl_xor_sync(0xffffffffu, acc.y, 16);
    acc.z += __shfl_xor_sync(0xffffffffu, acc.z, 16);
    acc.w += __shfl_xor_sync(0xffffffffu, acc.w, 16);
    if (half == 0) {
        float sc = 1.0f / (float)max(c, 1);
        ((float4*)(outp + (size_t)node * 64))[q] =
            make_float4(acc.x * sc, acc.y * sc, acc.z * sc, acc.w * sc);
    }
}

// ---------------- fused GEMM: 64-row x 128-col tile, 128 thr, 8x8 micro -----
// MODE 1: h = relu([agg1 | x] @ [W_l1 ; W_r1] + b1)          (K=64+64, C=128)
// MODE 2: [t | r2] = h @ [W_l2 | W_r2];  t -> outA, r2+b2 -> outB (K=128)
template <int MODE>
__global__ void __launch_bounds__(128)
gemm_kernel(const float* __restrict__ A0, const float* __restrict__ A1,
            const float* __restrict__ Wa, const float* __restrict__ Wb,
            const float* __restrict__ bias,
            float* __restrict__ outA, float* __restrict__ outB) {
    extern __shared__ float smem[];
    float* sW = smem;              // 128 x 128  [k][c]
    float* sA = smem + 128 * 128;  // 64 x 128   [row][k]
    float* sB = sA + 64 * 128;     // 128
    const int tid = threadIdx.x;
    const int base = blockIdx.x * 64;

    // ---- stage W ----
    {
        float4* sw4 = (float4*)sW;
        const float4* wa4 = (const float4*)Wa;
        const float4* wb4 = (const float4*)Wb;
#pragma unroll
        for (int i = 0; i < 32; i++) {
            int p = tid + 128 * i;
            int k = p >> 5, c4 = p & 31;
            float4 v;
            if (MODE == 1)   // rows stacked: [W_l1 (64x128); W_r1 (64x128)]
                v = (k < 64) ? __ldg(&wa4[k * 32 + c4]) : __ldg(&wb4[(k - 64) * 32 + c4]);
            else             // cols concat: [W_l2 (128x64) | W_r2 (128x64)]
                v = (c4 < 16) ? __ldg(&wa4[k * 16 + c4]) : __ldg(&wb4[k * 16 + c4 - 16]);
            sw4[p] = v;
        }
        sB[tid] = (MODE == 1) ? __ldg(&bias[tid])
                              : (tid < 64 ? 0.0f : __ldg(&bias[tid - 64]));
    }
    // ---- stage A (64 rows x 128 k) ----
    {
        float4* sa4 = (float4*)sA;
#pragma unroll
        for (int i = 0; i < 16; i++) {
            int p = tid + 128 * i;
            int rl = p >> 5, kc = p & 31;
            int row = base + rl;
            float4 v = make_float4(0.f, 0.f, 0.f, 0.f);
            if (row < N_NODES) {
                if (MODE == 1)
                    v = (kc < 16) ? __ldg((const float4*)(A0 + (size_t)row * 64) + kc)
                                  : __ldg((const float4*)(A1 + (size_t)row * 64) + (kc - 16));
                else
                    v = __ldg((const float4*)(A0 + (size_t)row * 128) + kc);
            }
            sa4[p] = v;
        }
    }
    __syncthreads();

    // ---- compute: 8 rows x 8 cols per thread, f32x2 accumulators ----
    const int cx = tid & 15;   // cols 8*cx .. 8*cx+7
    const int ry = tid >> 4;   // rows 8*ry .. 8*ry+7  (broadcast-friendly: 2/warp)
    unsigned long long acc[8][4];
#pragma unroll
    for (int j = 0; j < 8; j++)
#pragma unroll
        for (int p = 0; p < 4; p++) acc[j][p] = 0ull;

    const float4* a4base = (const float4*)(sA + ry * 8 * 128);
    for (int k4 = 0; k4 < 32; k4++) {
        float4 a4[8];
#pragma unroll
        for (int j = 0; j < 8; j++) a4[j] = a4base[j * 32 + k4];
#pragma unroll
        for (int kk = 0; kk < 4; kk++) {
            const float4* w4 = (const float4*)(sW + (k4 * 4 + kk) * 128);
            float4 w0 = w4[2 * cx], w1 = w4[2 * cx + 1];
            unsigned long long w01 = pk2(w0.x, w0.y);
            unsigned long long w23 = pk2(w0.z, w0.w);
            unsigned long long w45 = pk2(w1.x, w1.y);
            unsigned long long w67 = pk2(w1.z, w1.w);
#pragma unroll
            for (int j = 0; j < 8; j++) {
                float av = (kk == 0) ? a4[j].x : (kk == 1) ? a4[j].y
                         : (kk == 2) ? a4[j].z : a4[j].w;
                unsigned long long a2 = pk2(av, av);
                fma2(acc[j][0], a2, w01);
                fma2(acc[j][1], a2, w23);
                fma2(acc[j][2], a2, w45);
                fma2(acc[j][3], a2, w67);
            }
        }
    }

    // ---- epilogue ----
    const int c0 = 8 * cx;
    float bb[8];
#pragma unroll
    for (int t = 0; t < 8; t++) bb[t] = sB[c0 + t];
#pragma unroll
    for (int j = 0; j < 8; j++) {
        int row = base + ry * 8 + j;
        if (row >= N_NODES) continue;
        float o[8];
#pragma unroll
        for (int p = 0; p < 4; p++) {
            float2 v = upk2(acc[j][p]);
            o[2 * p]     = v.x + bb[2 * p];
            o[2 * p + 1] = v.y + bb[2 * p + 1];
        }
        if (MODE == 1) {
#pragma unroll
            for (int t = 0; t < 8; t++) o[t] = fmaxf(o[t], 0.0f);
            float4* d0 = (float4*)(outA + (size_t)row * 128 + c0);
            d0[0] = make_float4(o[0], o[1], o[2], o[3]);
            d0[1] = make_float4(o[4], o[5], o[6], o[7]);
        } else {
            float4* d0 = (c0 < 64)
                ? (float4*)(outA + (size_t)row * 64 + c0)
                : (float4*)(outB + (size_t)row * 64 + (c0 - 64));
            d0[0] = make_float4(o[0], o[1], o[2], o[3]);
            d0[1] = make_float4(o[4], o[5], o[6], o[7]);
        }
    }
}

// ---------------- finalize: out = sigmoid(agg2 + r2) -------------------------
__global__ void finalize_kernel(const float* __restrict__ agg2,
                                float* __restrict__ out) {
    int i = blockIdx.x * blockDim.x + threadIdx.x;   // float4 index
    if (i >= N_NODES * 16) return;
    float4 a = __ldg((const float4*)agg2 + i);
    float4 r = ((const float4*)out)[i];
    float4 o;
    o.x = 1.0f / (1.0f + expf(-(a.x + r.x)));
    o.y = 1.0f / (1.0f + expf(-(a.y + r.y)));
    o.z = 1.0f / (1.0f + expf(-(a.z + r.z)));
    o.w = 1.0f / (1.0f + expf(-(a.w + r.w)));
    ((float4*)out)[i] = o;
}

// ---------------- launch ------------------------------------------------------
extern "C" void kernel_launch(void* const* d_in, const int* in_sizes, int n_in,
                              void* d_out, int out_size) {
    const float* x    = (const float*)d_in[0];
    const int*   ei   = (const int*)d_in[1];
    const float* W_l1 = (const float*)d_in[2];
    const float* W_r1 = (const float*)d_in[3];
    const float* b1   = (const float*)d_in[4];
    const float* W_l2 = (const float*)d_in[5];
    const float* W_r2 = (const float*)d_in[6];
    const float* b2   = (const float*)d_in[7];
    const int* src = ei;
    const int* dst = ei + N_EDGES;
    float* out = (float*)d_out;

    void *p_agg1, *p_agg2, *p_cnt, *p_h, *p_t;
    cudaGetSymbolAddress(&p_agg1, g_agg1);
    cudaGetSymbolAddress(&p_agg2, g_agg2);
    cudaGetSymbolAddress(&p_cnt,  g_cnt);
    cudaGetSymbolAddress(&p_h,    g_h);
    cudaGetSymbolAddress(&p_t,    g_t);

    // ---- CSR build (once; reused for both layers) ----
    cudaMemsetAsync(p_cnt, 0, (size_t)N_NODES * sizeof(int));
    count_kernel<<<(N_EDGES + 255) / 256, 256>>>(dst);
    reduce_kernel<<<NB, SCAN_B>>>();
    scanblock_kernel<<<1, 256>>>();
    scatteroff_kernel<<<NB, SCAN_B>>>();
    fill_kernel<<<(N_EDGES + 255) / 256, 256>>>(src, dst);

    // ---- layer 1 ----
    agg_kernel<<<(N_NODES + 7) / 8, 256>>>(x, (float*)p_agg1);

    const int smem = (128 * 128 + 64 * 128 + 128) * (int)sizeof(float);
    cudaFuncSetAttribute(gemm_kernel<1>, cudaFuncAttributeMaxDynamicSharedMemorySize, smem);
    cudaFuncSetAttribute(gemm_kernel<2>, cudaFuncAttributeMaxDynamicSharedMemorySize, smem);
    const int gemm_blocks = (N_NODES + 63) / 64;

    gemm_kernel<1><<<gemm_blocks, 128, smem>>>((const float*)p_agg1, x,
                                               W_l1, W_r1, b1,
                                               (float*)p_h, (float*)nullptr);
    // ---- layer 2 (project first, aggregate 64ch) ----
    gemm_kernel<2><<<gemm_blocks, 128, smem>>>((const float*)p_h, (const float*)nullptr,
                                               W_l2, W_r2, b2,
                                               (float*)p_t, out);
    agg_kernel<<<(N_NODES + 7) / 8, 256>>>((const float*)p_t, (float*)p_agg2);
    finalize_kernel<<<(N_NODES * 16 + 255) / 256, 256>>>((const float*)p_agg2, out);
}

// round 9
// speedup vs baseline: 1.2232x; 1.0001x over previous
#include <cuda_runtime.h>
#include <math.h>

#define N_NODES 100000
#define N_EDGES 1600000
#define SCAN_B 512
#define NB ((N_NODES + SCAN_B - 1) / SCAN_B)   // 196

// ---------------- scratch (device globals; no allocation allowed) ----------
__device__ float g_agg1[(size_t)N_NODES * 64];   // mean-agg of x
__device__ float g_h   [(size_t)N_NODES * 128];  // layer-1 output
__device__ float g_t   [(size_t)N_NODES * 64];   // h @ W_l2 (projected)
__device__ int   g_cnt [N_NODES];
__device__ int   g_off [N_NODES];
__device__ int   g_pos [N_NODES];
__device__ int   g_adj [N_EDGES];
__device__ int   g_blocksum[NB];
__device__ int   g_blockoff[NB];

// ---------------- f32x2 helpers --------------------------------------------
__device__ __forceinline__ unsigned long long pk2(float x, float y) {
    unsigned long long r;
    asm("mov.b64 %0, {%1, %2};" : "=l"(r) : "f"(x), "f"(y));
    return r;
}
__device__ __forceinline__ void fma2(unsigned long long& d, unsigned long long a,
                                     unsigned long long b) {
    asm("fma.rn.f32x2 %0, %1, %2, %3;" : "=l"(d) : "l"(a), "l"(b), "l"(d));
}
__device__ __forceinline__ float2 upk2(unsigned long long v) {
    float2 f;
    asm("mov.b64 {%0, %1}, %2;" : "=f"(f.x), "=f"(f.y) : "l"(v));
    return f;
}

// ---------------- CSR construction ------------------------------------------
__global__ void count_kernel(const int* __restrict__ dst) {
    int i = blockIdx.x * blockDim.x + threadIdx.x;
    if (i < N_EDGES) atomicAdd(&g_cnt[dst[i]], 1);
}

__global__ void reduce_kernel() {   // grid NB, block SCAN_B
    __shared__ int s[SCAN_B / 32];
    int i = blockIdx.x * SCAN_B + threadIdx.x;
    int v = (i < N_NODES) ? g_cnt[i] : 0;
#pragma unroll
    for (int o = 16; o > 0; o >>= 1) v += __shfl_down_sync(0xffffffffu, v, o);
    if ((threadIdx.x & 31) == 0) s[threadIdx.x >> 5] = v;
    __syncthreads();
    if (threadIdx.x == 0) {
        int t = 0;
#pragma unroll
        for (int w = 0; w < SCAN_B / 32; w++) t += s[w];
        g_blocksum[blockIdx.x] = t;
    }
}

__global__ void scanblock_kernel() {   // 1 block, 256 threads
    __shared__ int s[256];
    int v = (threadIdx.x < NB) ? g_blocksum[threadIdx.x] : 0;
    s[threadIdx.x] = v;
    __syncthreads();
    for (int d = 1; d < 256; d <<= 1) {
        int t = (threadIdx.x >= d) ? s[threadIdx.x - d] : 0;
        __syncthreads();
        s[threadIdx.x] += t;
        __syncthreads();
    }
    if (threadIdx.x < NB)
        g_blockoff[threadIdx.x] = (threadIdx.x == 0) ? 0 : s[threadIdx.x - 1];
}

__global__ void scatteroff_kernel() {   // grid NB, block SCAN_B
    __shared__ int s[SCAN_B];
    int b = blockIdx.x;
    int i = b * SCAN_B + threadIdx.x;
    int v = (i < N_NODES) ? g_cnt[i] : 0;
    s[threadIdx.x] = v;
    __syncthreads();
    for (int d = 1; d < SCAN_B; d <<= 1) {
        int t = (threadIdx.x >= d) ? s[threadIdx.x - d] : 0;
        __syncthreads();
        s[threadIdx.x] += t;
        __syncthreads();
    }
    if (i < N_NODES) {
        int excl = s[threadIdx.x] - v + g_blockoff[b];
        g_off[i] = excl;
        g_pos[i] = excl;
    }
}

__global__ void fill_kernel(const int* __restrict__ src, const int* __restrict__ dst) {
    int e = blockIdx.x * blockDim.x + threadIdx.x;
    if (e < N_EDGES) {
        int d = dst[e];
        int p = atomicAdd(&g_pos[d], 1);
        g_adj[p] = src[e];
    }
}

// ---------------- pull aggregation: out[n] = mean_{s in adj(n)} feat[s] ------
// One warp per node; 2 halves of 16 lanes each walk alternate neighbors with
// 4-deep load pipelining (MLP=4 adj + 4 row-gathers in flight per half).
// FIN=1 fuses the layer-2 epilogue: out = sigmoid(mean + r2).
template <int FIN>
__global__ void __launch_bounds__(256)
agg_kernel(const float* __restrict__ feat, float* __restrict__ outp) {
    int node = blockIdx.x * 8 + (threadIdx.x >> 5);
    if (node >= N_NODES) return;
    int lane = threadIdx.x & 31;
    int half = lane >> 4;
    int q = lane & 15;
    int off = __ldg(&g_off[node]);
    int c = __ldg(&g_cnt[node]);
    const int* adj = g_adj + off;
    float4 acc = make_float4(0.f, 0.f, 0.f, 0.f);
    int i = half;
    for (; i + 6 < c; i += 8) {
        int s0 = __ldg(&adj[i]);
        int s1 = __ldg(&adj[i + 2]);
        int s2 = __ldg(&adj[i + 4]);
        int s3 = __ldg(&adj[i + 6]);
        float4 v0 = __ldg((const float4*)(feat + (size_t)s0 * 64) + q);
        float4 v1 = __ldg((const float4*)(feat + (size_t)s1 * 64) + q);
        float4 v2 = __ldg((const float4*)(feat + (size_t)s2 * 64) + q);
        float4 v3 = __ldg((const float4*)(feat + (size_t)s3 * 64) + q);
        acc.x += (v0.x + v1.x) + (v2.x + v3.x);
        acc.y += (v0.y + v1.y) + (v2.y + v3.y);
        acc.z += (v0.z + v1.z) + (v2.z + v3.z);
        acc.w += (v0.w + v1.w) + (v2.w + v3.w);
    }
    for (; i < c; i += 2) {
        int s0 = __ldg(&adj[i]);
        float4 v0 = __ldg((const float4*)(feat + (size_t)s0 * 64) + q);
        acc.x += v0.x; acc.y += v0.y; acc.z += v0.z; acc.w += v0.w;
    }
    acc.x += __shfl_xor_sync(0xffffffffu, acc.x, 16);
    acc.y += __shfl_xor_sync(0xffffffffu, acc.y, 16);
    acc.z += __shfl_xor_sync(0xffffffffu, acc.z, 16);
    acc.w += __shfl_xor_sync(0xffffffffu, acc.w, 16);
    if (half == 0) {
        float sc = 1.0f / (float)max(c, 1);
        float4* dp = (float4*)(outp + (size_t)node * 64) + q;
        if (FIN) {
            float4 r = *dp;   // r2 written by gemm2
            float4 o;
            o.x = 1.0f / (1.0f + expf(-(acc.x * sc + r.x)));
            o.y = 1.0f / (1.0f + expf(-(acc.y * sc + r.y)));
            o.z = 1.0f / (1.0f + expf(-(acc.z * sc + r.z)));
            o.w = 1.0f / (1.0f + expf(-(acc.w * sc + r.w)));
            *dp = o;
        } else {
            *dp = make_float4(acc.x * sc, acc.y * sc, acc.z * sc, acc.w * sc);
        }
    }
}

// ---------------- fused GEMM: 64-row x 128-col tile, 128 thr, 8x8 micro -----
// MODE 1: h = relu([agg1 | x] @ [W_l1 ; W_r1] + b1)          (K=64+64, C=128)
// MODE 2: [t | r2] = h @ [W_l2 | W_r2];  t -> outA, r2+b2 -> outB (K=128)
template <int MODE>
__global__ void __launch_bounds__(128)
gemm_kernel(const float* __restrict__ A0, const float* __restrict__ A1,
            const float* __restrict__ Wa, const float* __restrict__ Wb,
            const float* __restrict__ bias,
            float* __restrict__ outA, float* __restrict__ outB) {
    extern __shared__ float smem[];
    float* sW = smem;              // 128 x 128  [k][c]
    float* sA = smem + 128 * 128;  // 64 x 128   [row][k]
    float* sB = sA + 64 * 128;     // 128
    const int tid = threadIdx.x;
    const int base = blockIdx.x * 64;

    // ---- stage W ----
    {
        float4* sw4 = (float4*)sW;
        const float4* wa4 = (const float4*)Wa;
        const float4* wb4 = (const float4*)Wb;
#pragma unroll
        for (int i = 0; i < 32; i++) {
            int p = tid + 128 * i;
            int k = p >> 5, c4 = p & 31;
            float4 v;
            if (MODE == 1)   // rows stacked: [W_l1 (64x128); W_r1 (64x128)]
                v = (k < 64) ? __ldg(&wa4[k * 32 + c4]) : __ldg(&wb4[(k - 64) * 32 + c4]);
            else             // cols concat: [W_l2 (128x64) | W_r2 (128x64)]
                v = (c4 < 16) ? __ldg(&wa4[k * 16 + c4]) : __ldg(&wb4[k * 16 + c4 - 16]);
            sw4[p] = v;
        }
        sB[tid] = (MODE == 1) ? __ldg(&bias[tid])
                              : (tid < 64 ? 0.0f : __ldg(&bias[tid - 64]));
    }
    // ---- stage A (64 rows x 128 k) ----
    {
        float4* sa4 = (float4*)sA;
#pragma unroll
        for (int i = 0; i < 16; i++) {
            int p = tid + 128 * i;
            int rl = p >> 5, kc = p & 31;
            int row = base + rl;
            float4 v = make_float4(0.f, 0.f, 0.f, 0.f);
            if (row < N_NODES) {
                if (MODE == 1)
                    v = (kc < 16) ? __ldg((const float4*)(A0 + (size_t)row * 64) + kc)
                                  : __ldg((const float4*)(A1 + (size_t)row * 64) + (kc - 16));
                else
                    v = __ldg((const float4*)(A0 + (size_t)row * 128) + kc);
            }
            sa4[p] = v;
        }
    }
    __syncthreads();

    // ---- compute: 8 rows x 8 cols per thread, f32x2 accumulators ----
    const int cx = tid & 15;   // cols 8*cx .. 8*cx+7
    const int ry = tid >> 4;   // rows 8*ry .. 8*ry+7
    unsigned long long acc[8][4];
#pragma unroll
    for (int j = 0; j < 8; j++)
#pragma unroll
        for (int p = 0; p < 4; p++) acc[j][p] = 0ull;

    const float4* a4base = (const float4*)(sA + ry * 8 * 128);
    for (int k4 = 0; k4 < 32; k4++) {
        float4 a4[8];
#pragma unroll
        for (int j = 0; j < 8; j++) a4[j] = a4base[j * 32 + k4];
#pragma unroll
        for (int kk = 0; kk < 4; kk++) {
            const float4* w4 = (const float4*)(sW + (k4 * 4 + kk) * 128);
            float4 w0 = w4[2 * cx], w1 = w4[2 * cx + 1];
            unsigned long long w01 = pk2(w0.x, w0.y);
            unsigned long long w23 = pk2(w0.z, w0.w);
            unsigned long long w45 = pk2(w1.x, w1.y);
            unsigned long long w67 = pk2(w1.z, w1.w);
#pragma unroll
            for (int j = 0; j < 8; j++) {
                float av = (kk == 0) ? a4[j].x : (kk == 1) ? a4[j].y
                         : (kk == 2) ? a4[j].z : a4[j].w;
                unsigned long long a2 = pk2(av, av);
                fma2(acc[j][0], a2, w01);
                fma2(acc[j][1], a2, w23);
                fma2(acc[j][2], a2, w45);
                fma2(acc[j][3], a2, w67);
            }
        }
    }

    // ---- epilogue ----
    const int c0 = 8 * cx;
    float bb[8];
#pragma unroll
    for (int t = 0; t < 8; t++) bb[t] = sB[c0 + t];
#pragma unroll
    for (int j = 0; j < 8; j++) {
        int row = base + ry * 8 + j;
        if (row >= N_NODES) continue;
        float o[8];
#pragma unroll
        for (int p = 0; p < 4; p++) {
            float2 v = upk2(acc[j][p]);
            o[2 * p]     = v.x + bb[2 * p];
            o[2 * p + 1] = v.y + bb[2 * p + 1];
        }
        if (MODE == 1) {
#pragma unroll
            for (int t = 0; t < 8; t++) o[t] = fmaxf(o[t], 0.0f);
            float4* d0 = (float4*)(outA + (size_t)row * 128 + c0);
            d0[0] = make_float4(o[0], o[1], o[2], o[3]);
            d0[1] = make_float4(o[4], o[5], o[6], o[7]);
        } else {
            float4* d0 = (c0 < 64)
                ? (float4*)(outA + (size_t)row * 64 + c0)
                : (float4*)(outB + (size_t)row * 64 + (c0 - 64));
            d0[0] = make_float4(o[0], o[1], o[2], o[3]);
            d0[1] = make_float4(o[4], o[5], o[6], o[7]);
        }
    }
}

// ---------------- launch ------------------------------------------------------
extern "C" void kernel_launch(void* const* d_in, const int* in_sizes, int n_in,
                              void* d_out, int out_size) {
    const float* x    = (const float*)d_in[0];
    const int*   ei   = (const int*)d_in[1];
    const float* W_l1 = (const float*)d_in[2];
    const float* W_r1 = (const float*)d_in[3];
    const float* b1   = (const float*)d_in[4];
    const float* W_l2 = (const float*)d_in[5];
    const float* W_r2 = (const float*)d_in[6];
    const float* b2   = (const float*)d_in[7];
    const int* src = ei;
    const int* dst = ei + N_EDGES;
    float* out = (float*)d_out;

    void *p_agg1, *p_cnt, *p_h, *p_t;
    cudaGetSymbolAddress(&p_agg1, g_agg1);
    cudaGetSymbolAddress(&p_cnt,  g_cnt);
    cudaGetSymbolAddress(&p_h,    g_h);
    cudaGetSymbolAddress(&p_t,    g_t);

    // ---- CSR build (once; reused for both layers) ----
    cudaMemsetAsync(p_cnt, 0, (size_t)N_NODES * sizeof(int));
    count_kernel<<<(N_EDGES + 255) / 256, 256>>>(dst);
    reduce_kernel<<<NB, SCAN_B>>>();
    scanblock_kernel<<<1, 256>>>();
    scatteroff_kernel<<<NB, SCAN_B>>>();
    fill_kernel<<<(N_EDGES + 255) / 256, 256>>>(src, dst);

    // ---- layer 1 ----
    agg_kernel<0><<<(N_NODES + 7) / 8, 256>>>(x, (float*)p_agg1);

    const int smem = (128 * 128 + 64 * 128 + 128) * (int)sizeof(float);
    cudaFuncSetAttribute(gemm_kernel<1>, cudaFuncAttributeMaxDynamicSharedMemorySize, smem);
    cudaFuncSetAttribute(gemm_kernel<2>, cudaFuncAttributeMaxDynamicSharedMemorySize, smem);
    const int gemm_blocks = (N_NODES + 63) / 64;

    gemm_kernel<1><<<gemm_blocks, 128, smem>>>((const float*)p_agg1, x,
                                               W_l1, W_r1, b1,
                                               (float*)p_h, (float*)nullptr);
    // ---- layer 2 (project first, aggregate 64ch, fused finalize) ----
    gemm_kernel<2><<<gemm_blocks, 128, smem>>>((const float*)p_h, (const float*)nullptr,
                                               W_l2, W_r2, b2,
                                               (float*)p_t, out);
    agg_kernel<1><<<(N_NODES + 7) / 8, 256>>>((const float*)p_t, out);
}